// round 8
// baseline (speedup 1.0000x reference)
#include <cuda_runtime.h>
#include <cuda_fp16.h>
#include <cstdint>

#define BB  32
#define SS  2048
#define DD  768
#define QDIM 256
#define ODIM 1024
#define STAGES 3
#define PITCH 72                       // halves per smem row (144 B)
#define ATILE (128 * PITCH)            // halves per A tile
#define STGH  (2 * ATILE)              // halves per stage (A+B)

// -------- scratch (allocation-free: __device__ globals) --------
__device__ __half g_dataH[(size_t)BB * SS * DD];
__device__ __half g_W1h[QDIM * DD];
__device__ __half g_W2h[QDIM * DD];
__device__ __half g_Qh [(size_t)BB * SS * QDIM];
__device__ __half g_Kh [(size_t)BB * SS * QDIM];
__device__ __half g_KTh[(size_t)BB * QDIM * SS];   // K transposed [b][q][s]
__device__ __half g_EH [(size_t)BB * SS * SS];     // exp(scores) fp16 (256 MB)
__device__ float  g_RS [BB * SS];                  // row sums of exp
__device__ float  g_XT [(size_t)BB * QDIM * SS];   // attn out transposed [b][q][s]
__device__ float  g_XMAX[BB * QDIM];

__device__ __forceinline__ uint32_t smem_u32(const void* p) {
    uint32_t a;
    asm("{ .reg .u64 t; cvta.to.shared.u64 t, %1; cvt.u32.u64 %0, t; }" : "=r"(a) : "l"(p));
    return a;
}
__device__ __forceinline__ void cp16(uint32_t dst, const void* src) {
    asm volatile("cp.async.cg.shared.global [%0], [%1], 16;" :: "r"(dst), "l"(src));
}
#define CP_COMMIT() asm volatile("cp.async.commit_group;" ::: "memory")
#define CP_WAIT(n)  asm volatile("cp.async.wait_group %0;" :: "n"(n) : "memory")

__device__ __forceinline__ void ldsm4(uint32_t& r0, uint32_t& r1, uint32_t& r2,
                                      uint32_t& r3, uint32_t addr) {
    asm volatile("ldmatrix.sync.aligned.m8n8.x4.shared.b16 {%0,%1,%2,%3}, [%4];"
                 : "=r"(r0), "=r"(r1), "=r"(r2), "=r"(r3) : "r"(addr));
}

__device__ __forceinline__ void mma16(float* d, const uint32_t* a, const uint32_t* b) {
    asm volatile(
        "mma.sync.aligned.m16n8k16.row.col.f32.f16.f16.f32 "
        "{%0,%1,%2,%3}, {%4,%5,%6,%7}, {%8,%9}, {%0,%1,%2,%3};"
        : "+f"(d[0]), "+f"(d[1]), "+f"(d[2]), "+f"(d[3])
        : "r"(a[0]), "r"(a[1]), "r"(a[2]), "r"(a[3]), "r"(b[0]), "r"(b[1]));
}

// ============================================================================
// fp16 NT GEMM, cp.async 3-stage pipeline, k-chunk 64, ldmatrix fragments.
// CTA 128x128, 256 thr (8 warps 2x4), warp tile 64x32.
// A [M,K], B [N,K] fp16 row-major.
//   EPI=1: C fp16, + bias
//   EPI=2: C fp16 + bias, ALSO CT fp16 transposed per-batch [QDIM][SS] (proj-K)
//   EPI=3: C fp16 = exp(acc*scale); per-row sums atomically added to aux[b*SS+m]
//   EPI=4: C fp32 = acc / aux[b*SS+n]   (column-wise normalization)
// Smem rows padded to 72 halves (144B): conflict-free ldmatrix + cp.async.
// Requires M%128==0, N%128==0, kdim%64==0.
// ============================================================================
template <int EPI>
__global__ __launch_bounds__(256, 2) void hgemm(
    const __half* __restrict__ A, const __half* __restrict__ B,
    const float* __restrict__ bias, void* __restrict__ Cv,
    __half* __restrict__ CT, float* __restrict__ aux,
    int lda, int ldb, int ldc, int kdim, float scale,
    size_t sA, size_t sB, size_t sC)
{
    extern __shared__ __half sm[];
    A += (size_t)blockIdx.z * sA;
    B += (size_t)blockIdx.z * sB;
    const int bm = blockIdx.y * 128;
    const int bn = blockIdx.x * 128;

    const int tid = threadIdx.x;
    const int lane = tid & 31, wid = tid >> 5;
    const int wm = wid & 1, wn = wid >> 1;      // warp 64m x 32n
    const int qd = lane >> 2, cc = lane & 3;

    // loader: thread covers row = tid>>1, halves [seg, seg+32) (4 x cp16)
    const int lrow = tid >> 1;
    const int lseg = (tid & 1) * 32;
    const __half* pa = A + (size_t)(bm + lrow) * lda + lseg;
    const __half* pb = B + (size_t)(bn + lrow) * ldb + lseg;
    const uint32_t smb = smem_u32(sm);
    const uint32_t dA = smb + (uint32_t)(lrow * PITCH + lseg) * 2;
    const uint32_t dB = dA + ATILE * 2;
    const uint32_t STG = STGH * 2;              // bytes per stage

    // ldmatrix per-lane offsets (relative to stage base, ks=0)
    uint32_t aoff[4], boff[2];
#pragma unroll
    for (int mt = 0; mt < 4; mt++)
        aoff[mt] = (uint32_t)(((wm * 64 + mt * 16 + (lane & 7) + (lane & 8)) * PITCH
                               + ((lane >> 4) * 8)) * 2);
#pragma unroll
    for (int np = 0; np < 2; np++)
        boff[np] = (uint32_t)(ATILE * 2
                   + ((wn * 32 + np * 16 + (lane & 7) + ((lane >> 4) * 8)) * PITCH
                      + (lane & 8)) * 2);

    float acc[4][4][4];
#pragma unroll
    for (int i = 0; i < 4; i++)
#pragma unroll
        for (int j = 0; j < 4; j++)
#pragma unroll
            for (int r = 0; r < 4; r++) acc[i][j][r] = 0.f;

    const int nc = kdim >> 6;                   // chunks of 64

    // prologue: stages 0..STAGES-2
#pragma unroll
    for (int s = 0; s < STAGES - 1; s++) {
        if (s < nc) {
            const size_t k0 = (size_t)s * 64;
            const uint32_t da = dA + s * STG, db = dB + s * STG;
#pragma unroll
            for (int i = 0; i < 4; i++) {
                cp16(da + i * 16, pa + k0 + i * 8);
                cp16(db + i * 16, pb + k0 + i * 8);
            }
        }
        CP_COMMIT();
    }

    int st = 0;                                  // stage index of chunk ch
    for (int ch = 0; ch < nc; ch++) {
        CP_WAIT(STAGES - 2);
        __syncthreads();   // stage ch ready; everyone done reading stage ch-1

        // refill the stage freed by chunk ch-1
        {
            const int nxt = ch + STAGES - 1;
            if (nxt < nc) {
                int fs = st + STAGES - 1; if (fs >= STAGES) fs -= STAGES;
                const size_t k0 = (size_t)nxt * 64;
                const uint32_t da = dA + fs * STG, db = dB + fs * STG;
#pragma unroll
                for (int i = 0; i < 4; i++) {
                    cp16(da + i * 16, pa + k0 + i * 8);
                    cp16(db + i * 16, pb + k0 + i * 8);
                }
            }
            CP_COMMIT();
        }

        const uint32_t sa = smb + (uint32_t)st * STG;
#pragma unroll
        for (int ks = 0; ks < 4; ks++) {
            uint32_t af[4][4], bf[4][2];
#pragma unroll
            for (int mt = 0; mt < 4; mt++)
                ldsm4(af[mt][0], af[mt][1], af[mt][2], af[mt][3],
                      sa + aoff[mt] + ks * 32);
#pragma unroll
            for (int np = 0; np < 2; np++)
                ldsm4(bf[2 * np][0], bf[2 * np][1], bf[2 * np + 1][0],
                      bf[2 * np + 1][1], sa + boff[np] + ks * 32);
#pragma unroll
            for (int mt = 0; mt < 4; mt++)
#pragma unroll
                for (int nt = 0; nt < 4; nt++)
                    mma16(acc[mt][nt], af[mt], bf[nt]);
        }
        if (++st == STAGES) st = 0;
    }

    // ---- epilogue ----
    float inv[4][2];
    if (EPI == 4) {
#pragma unroll
        for (int nt = 0; nt < 4; nt++) {
            const int n0 = bn + wn * 32 + nt * 8 + cc * 2;
            inv[nt][0] = 1.0f / __ldg(&aux[blockIdx.z * SS + n0]);
            inv[nt][1] = 1.0f / __ldg(&aux[blockIdx.z * SS + n0 + 1]);
        }
    }
    float* srs = (float*)sm;   // EPI==3: per-CTA row sums (128 floats)
    if (EPI == 3) {
        __syncthreads();       // all warps done reading pipeline smem
        if (tid < 128) srs[tid] = 0.f;
        __syncthreads();
    }

#pragma unroll
    for (int mt = 0; mt < 4; mt++) {
        const int m0 = bm + wm * 64 + mt * 16 + qd;
        float rs0 = 0.f, rs1 = 0.f;
#pragma unroll
        for (int nt = 0; nt < 4; nt++) {
            const int n0 = bn + wn * 32 + nt * 8 + cc * 2;
            float c0 = acc[mt][nt][0] * scale;
            float c1 = acc[mt][nt][1] * scale;
            float c2 = acc[mt][nt][2] * scale;
            float c3 = acc[mt][nt][3] * scale;
            if (EPI == 4) {
                c0 *= inv[nt][0]; c1 *= inv[nt][1];
                c2 *= inv[nt][0]; c3 *= inv[nt][1];
                float* Cf = (float*)Cv + (size_t)blockIdx.z * sC;
                *(float2*)(Cf + (size_t)m0 * ldc + n0)       = make_float2(c0, c1);
                *(float2*)(Cf + (size_t)(m0 + 8) * ldc + n0) = make_float2(c2, c3);
            } else if (EPI == 3) {
                c0 = __expf(c0); c1 = __expf(c1);
                c2 = __expf(c2); c3 = __expf(c3);
                rs0 += c0 + c1; rs1 += c2 + c3;
                __half2 h0 = __floats2half2_rn(c0, c1);
                __half2 h1 = __floats2half2_rn(c2, c3);
                __half* Ch = (__half*)Cv + (size_t)blockIdx.z * sC;
                *(__half2*)(Ch + (size_t)m0 * ldc + n0)       = h0;
                *(__half2*)(Ch + (size_t)(m0 + 8) * ldc + n0) = h1;
            } else {
                const float bx = bias[n0], by = bias[n0 + 1];
                c0 += bx; c1 += by; c2 += bx; c3 += by;
                __half2 h0 = __floats2half2_rn(c0, c1);
                __half2 h1 = __floats2half2_rn(c2, c3);
                __half* Ch = (__half*)Cv + (size_t)blockIdx.z * sC;
                *(__half2*)(Ch + (size_t)m0 * ldc + n0)       = h0;
                *(__half2*)(Ch + (size_t)(m0 + 8) * ldc + n0) = h1;
                if (EPI == 2) {
                    const int b0 = m0 >> 11, s0 = m0 & (SS - 1);
                    __half* t = CT + ((size_t)b0 * QDIM + n0) * SS + s0;
                    t[0]      = __low2half(h0);
                    t[SS]     = __high2half(h0);
                    t[8]      = __low2half(h1);
                    t[SS + 8] = __high2half(h1);
                }
            }
        }
        if (EPI == 3) {
            rs0 += __shfl_xor_sync(0xffffffffu, rs0, 1);
            rs0 += __shfl_xor_sync(0xffffffffu, rs0, 2);
            rs1 += __shfl_xor_sync(0xffffffffu, rs1, 1);
            rs1 += __shfl_xor_sync(0xffffffffu, rs1, 2);
            if (cc == 0) {
                atomicAdd(&srs[wm * 64 + mt * 16 + qd],     rs0);
                atomicAdd(&srs[wm * 64 + mt * 16 + qd + 8], rs1);
            }
        }
    }
    if (EPI == 3) {
        __syncthreads();
        if (tid < 128) atomicAdd(&aux[blockIdx.z * SS + bm + tid], srs[tid]);
    }
}

// ============================================================================
__global__ __launch_bounds__(256) void zero_rowsum(float* __restrict__ rs)
{
    const int i = blockIdx.x * 1024 + threadIdx.x * 4;
    *(float4*)(rs + i) = make_float4(0.f, 0.f, 0.f, 0.f);
}

// ============================================================================
// fp32 -> fp16 conversion (n % 8 == 0)
// ============================================================================
__global__ __launch_bounds__(256) void f2h_kernel(
    const float* __restrict__ s, __half* __restrict__ d, size_t n)
{
    const size_t i = ((size_t)blockIdx.x * 256 + threadIdx.x) * 8;
    if (i + 8 <= n) {
        float4 a = *(const float4*)(s + i);
        float4 b = *(const float4*)(s + i + 4);
        uint4 o;
        __half2 h;
        h = __floats2half2_rn(a.x, a.y); o.x = *(uint32_t*)&h;
        h = __floats2half2_rn(a.z, a.w); o.y = *(uint32_t*)&h;
        h = __floats2half2_rn(b.x, b.y); o.z = *(uint32_t*)&h;
        h = __floats2half2_rn(b.z, b.w); o.w = *(uint32_t*)&h;
        *(uint4*)(d + i) = o;
    }
}

// ============================================================================
// Contiguous row max over XT[b][q][0:2048] -> g_XMAX  (one warp per row)
// ============================================================================
__global__ __launch_bounds__(256) void maxpool_rows(const float* __restrict__ XT)
{
    const int r = blockIdx.x * 8 + (threadIdx.x >> 5);
    const int lane = threadIdx.x & 31;
    const float4* p = (const float4*)(XT + (size_t)r * SS);
    float m = -INFINITY;
#pragma unroll
    for (int i = 0; i < 16; i++) {
        float4 v = p[lane + i * 32];
        m = fmaxf(m, fmaxf(fmaxf(v.x, v.y), fmaxf(v.z, v.w)));
    }
#pragma unroll
    for (int o = 16; o > 0; o >>= 1) m = fmaxf(m, __shfl_xor_sync(0xffffffffu, m, o));
    if (lane == 0) g_XMAX[r] = m;
}

// ============================================================================
__global__ __launch_bounds__(256) void final_head(
    const float* __restrict__ W3, const float* __restrict__ b3,
    float* __restrict__ out)
{
    const int b = blockIdx.x;
    const int tid = threadIdx.x;
    __shared__ float xs[QDIM];
    xs[tid] = g_XMAX[b * QDIM + tid];
    __syncthreads();

#pragma unroll
    for (int kk = 0; kk < 4; kk++) {
        const int o = tid + kk * 256;
        const float4* w = (const float4*)(W3 + (size_t)o * QDIM);
        float acc = 0.f;
#pragma unroll
        for (int qq = 0; qq < QDIM / 4; qq++) {
            float4 wv = w[qq];
            acc += wv.x * xs[qq * 4 + 0] + wv.y * xs[qq * 4 + 1]
                 + wv.z * xs[qq * 4 + 2] + wv.w * xs[qq * 4 + 3];
        }
        out[(size_t)b * ODIM + o] = fmaxf(acc + b3[o], 0.f);
    }
}

// ============================================================================
extern "C" void kernel_launch(void* const* d_in, const int* in_sizes, int n_in,
                              void* d_out, int out_size)
{
    const float* data = (const float*)d_in[0];
    /* d_in[1] = seq_len: unused by the reference */
    const float* W1 = (const float*)d_in[2];
    const float* b1 = (const float*)d_in[3];
    const float* W2 = (const float*)d_in[4];
    const float* b2 = (const float*)d_in[5];
    const float* W3 = (const float*)d_in[6];
    const float* b3 = (const float*)d_in[7];
    float* out = (float*)d_out;

    __half *dataH, *W1h, *W2h, *Qh, *Kh, *KTh, *EH;
    float *RS, *XT;
    cudaGetSymbolAddress((void**)&dataH, g_dataH);
    cudaGetSymbolAddress((void**)&W1h, g_W1h);
    cudaGetSymbolAddress((void**)&W2h, g_W2h);
    cudaGetSymbolAddress((void**)&Qh,  g_Qh);
    cudaGetSymbolAddress((void**)&Kh,  g_Kh);
    cudaGetSymbolAddress((void**)&KTh, g_KTh);
    cudaGetSymbolAddress((void**)&EH,  g_EH);
    cudaGetSymbolAddress((void**)&RS,  g_RS);
    cudaGetSymbolAddress((void**)&XT,  g_XT);

    const int SMEM = STAGES * STGH * 2;   // 110592 B
    cudaFuncSetAttribute(hgemm<1>, cudaFuncAttributeMaxDynamicSharedMemorySize, SMEM);
    cudaFuncSetAttribute(hgemm<2>, cudaFuncAttributeMaxDynamicSharedMemorySize, SMEM);
    cudaFuncSetAttribute(hgemm<3>, cudaFuncAttributeMaxDynamicSharedMemorySize, SMEM);
    cudaFuncSetAttribute(hgemm<4>, cudaFuncAttributeMaxDynamicSharedMemorySize, SMEM);

    const size_t strQK = (size_t)SS * QDIM;
    const size_t strSC = (size_t)SS * SS;
    const float  inv_sqrt_qd = 1.0f / 16.0f;

    // 0) convert inputs to fp16; zero rowsum accumulator
    const size_t nd = (size_t)BB * SS * DD;
    f2h_kernel<<<(unsigned)(nd / (256 * 8)), 256>>>(data, dataH, nd);
    f2h_kernel<<<(QDIM * DD) / (256 * 8), 256>>>(W1, W1h, QDIM * DD);
    f2h_kernel<<<(QDIM * DD) / (256 * 8), 256>>>(W2, W2h, QDIM * DD);
    zero_rowsum<<<(BB * SS) / 1024, 256>>>(RS);

    // 1) Q = data @ W1^T + b1 -> fp16
    hgemm<1><<<dim3(QDIM / 128, (BB * SS) / 128, 1), 256, SMEM>>>(
        dataH, W1h, b1, Qh, nullptr, nullptr, DD, DD, QDIM, DD, 1.0f, 0, 0, 0);
    // 2) K = data @ W2^T + b2 -> fp16 + fp16 transposed
    hgemm<2><<<dim3(QDIM / 128, (BB * SS) / 128, 1), 256, SMEM>>>(
        dataH, W2h, b2, Kh, KTh, nullptr, DD, DD, QDIM, DD, 1.0f, 0, 0, 0);

    // 3) E[b] = exp((K[b] @ Q[b]^T) / 16) -> fp16, rowsums into RS
    hgemm<3><<<dim3(SS / 128, SS / 128, BB), 256, SMEM>>>(
        Kh, Qh, nullptr, EH, nullptr, RS, QDIM, QDIM, SS, QDIM, inv_sqrt_qd,
        strQK, strQK, strSC);

    // 4) XT[b][q][s] = (sum_j KT[b][q][j] * E[s][j]) / RS[b][s]  (NT, fp32 out)
    hgemm<4><<<dim3(SS / 128, QDIM / 128, BB), 256, SMEM>>>(
        KTh, EH, nullptr, XT, nullptr, RS, SS, SS, SS, SS, 1.0f,
        strQK, strSC, strQK);

    // 5) maxpool over contiguous s
    maxpool_rows<<<BB * QDIM / 8, 256>>>(XT);

    // 6) out = relu(xmax @ W3^T + b3)
    final_head<<<BB, 256>>>(W3, b3, out);
}

// round 9
// speedup vs baseline: 1.1841x; 1.1841x over previous
#include <cuda_runtime.h>
#include <cuda_fp16.h>
#include <cstdint>

#define BB  32
#define SS  2048
#define DD  768
#define QDIM 256
#define ODIM 1024
#define STAGES 4

// -------- scratch (allocation-free: __device__ globals) --------
__device__ __half g_dataH[(size_t)BB * SS * DD];
__device__ __half g_W1h[QDIM * DD];
__device__ __half g_W2h[QDIM * DD];
__device__ __half g_Qh [(size_t)BB * SS * QDIM];
__device__ __half g_Kh [(size_t)BB * SS * QDIM];
__device__ __half g_KTh[(size_t)BB * QDIM * SS];   // K transposed [b][q][s]
__device__ __half g_EH [(size_t)BB * SS * SS];     // exp(scores) fp16 (256 MB)
__device__ float  g_RS [BB * SS];                  // row sums of exp
__device__ float  g_XMAX[BB * QDIM];               // fused maxpool result

__device__ __forceinline__ uint32_t smem_u32(const void* p) {
    uint32_t a;
    asm("{ .reg .u64 t; cvta.to.shared.u64 t, %1; cvt.u32.u64 %0, t; }" : "=r"(a) : "l"(p));
    return a;
}
__device__ __forceinline__ void cp16(uint32_t dst, const void* src) {
    asm volatile("cp.async.cg.shared.global [%0], [%1], 16;" :: "r"(dst), "l"(src));
}
#define CP_COMMIT() asm volatile("cp.async.commit_group;" ::: "memory")
#define CP_WAIT(n)  asm volatile("cp.async.wait_group %0;" :: "n"(n) : "memory")

__device__ __forceinline__ void ldsm4(uint32_t& r0, uint32_t& r1, uint32_t& r2,
                                      uint32_t& r3, uint32_t addr) {
    asm volatile("ldmatrix.sync.aligned.m8n8.x4.shared.b16 {%0,%1,%2,%3}, [%4];"
                 : "=r"(r0), "=r"(r1), "=r"(r2), "=r"(r3) : "r"(addr));
}

__device__ __forceinline__ void mma16(float* d, const uint32_t* a, const uint32_t* b) {
    asm volatile(
        "mma.sync.aligned.m16n8k16.row.col.f32.f16.f16.f32 "
        "{%0,%1,%2,%3}, {%4,%5,%6,%7}, {%8,%9}, {%0,%1,%2,%3};"
        : "+f"(d[0]), "+f"(d[1]), "+f"(d[2]), "+f"(d[3])
        : "r"(a[0]), "r"(a[1]), "r"(a[2]), "r"(a[3]), "r"(b[0]), "r"(b[1]));
}

// exact, order-independent float atomic max (init must be -inf)
__device__ __forceinline__ void atomicMaxF(float* a, float v) {
    if (v >= 0.f) atomicMax((int*)a, __float_as_int(v));
    else          atomicMin((unsigned int*)a, __float_as_uint(v));
}

// ============================================================================
// fp16 NT GEMM, cp.async 4-stage pipeline + ldmatrix fragment loads.
// CTA 128x128, k-chunk 32, 256 thr (8 warps 2x4), warp tile 64x32.
// A [M,K], B [N,K] fp16 row-major.
//   EPI=1: C fp16, + bias
//   EPI=2: C fp16 + bias, ALSO CT fp16 transposed per-batch [QDIM][SS] (proj-K)
//   EPI=3: C fp16 = exp(acc*scale); per-row sums atomically added to aux[b*SS+m]
//   EPI=4: no C store; X[m,n] = acc / aux[b*SS+n]; row-max over n fused:
//          atomicMaxF into xmax[b*QDIM+m]
// Smem rows padded to 40 halves (80B): conflict-free ldmatrix.
// Requires M%128==0, N%128==0, kdim%32==0.
// ============================================================================
template <int EPI>
__global__ __launch_bounds__(256, 2) void hgemm(
    const __half* __restrict__ A, const __half* __restrict__ B,
    const float* __restrict__ bias, void* __restrict__ Cv,
    __half* __restrict__ CT, float* __restrict__ aux, float* __restrict__ xmax,
    int lda, int ldb, int ldc, int kdim, float scale,
    size_t sA, size_t sB, size_t sC)
{
    extern __shared__ __half sm[];
    A += (size_t)blockIdx.z * sA;
    B += (size_t)blockIdx.z * sB;
    const int bm = blockIdx.y * 128;
    const int bn = blockIdx.x * 128;

    const int tid = threadIdx.x;
    const int lane = tid & 31, wid = tid >> 5;
    const int wm = wid & 1, wn = wid >> 1;      // warp 64m x 32n
    const int qd = lane >> 2, cc = lane & 3;

    // loader: thread covers row = tid>>1, halves [seg, seg+16)
    const int lrow = tid >> 1;
    const int lseg = (tid & 1) * 16;
    const __half* pa = A + (size_t)(bm + lrow) * lda + lseg;
    const __half* pb = B + (size_t)(bn + lrow) * ldb + lseg;
    const uint32_t smb = smem_u32(sm);
    const uint32_t dA = smb + (uint32_t)(lrow * 40 + lseg) * 2;
    const uint32_t dB = dA + 5120 * 2;
    const uint32_t STG = 10240 * 2;             // bytes per stage (A+B)

    // ldmatrix per-lane offsets (relative to stage base, ks=0)
    uint32_t aoff[4], boff[2];
#pragma unroll
    for (int mt = 0; mt < 4; mt++)
        aoff[mt] = (uint32_t)(((wm * 64 + mt * 16 + (lane & 7) + (lane & 8)) * 40
                               + ((lane >> 4) * 8)) * 2);
#pragma unroll
    for (int np = 0; np < 2; np++)
        boff[np] = (uint32_t)(5120 * 2
                   + ((wn * 32 + np * 16 + (lane & 7) + ((lane >> 4) * 8)) * 40
                      + (lane & 8)) * 2);

    float acc[4][4][4];
#pragma unroll
    for (int i = 0; i < 4; i++)
#pragma unroll
        for (int j = 0; j < 4; j++)
#pragma unroll
            for (int r = 0; r < 4; r++) acc[i][j][r] = 0.f;

    const int nc = kdim >> 5;

    // prologue: stages 0..STAGES-2
#pragma unroll
    for (int s = 0; s < STAGES - 1; s++) {
        if (s < nc) {
            const size_t k0 = (size_t)s * 32;
            const uint32_t da = dA + s * STG, db = dB + s * STG;
            cp16(da,      pa + k0);
            cp16(da + 16, pa + k0 + 8);
            cp16(db,      pb + k0);
            cp16(db + 16, pb + k0 + 8);
        }
        CP_COMMIT();
    }

    for (int ch = 0; ch < nc; ch++) {
        CP_WAIT(STAGES - 2);
        __syncthreads();   // stage ch ready; everyone done reading stage ch-1

        // refill the stage freed by chunk ch-1
        {
            const int nxt = ch + STAGES - 1;
            if (nxt < nc) {
                const int st = nxt & (STAGES - 1);
                const size_t k0 = (size_t)nxt * 32;
                const uint32_t da = dA + st * STG, db = dB + st * STG;
                cp16(da,      pa + k0);
                cp16(da + 16, pa + k0 + 8);
                cp16(db,      pb + k0);
                cp16(db + 16, pb + k0 + 8);
            }
            CP_COMMIT();
        }

        const uint32_t sa = smb + (uint32_t)(ch & (STAGES - 1)) * STG;
#pragma unroll
        for (int ks = 0; ks < 2; ks++) {
            uint32_t af[4][4], bf[4][2];
#pragma unroll
            for (int mt = 0; mt < 4; mt++)
                ldsm4(af[mt][0], af[mt][1], af[mt][2], af[mt][3],
                      sa + aoff[mt] + ks * 32);
#pragma unroll
            for (int np = 0; np < 2; np++)
                ldsm4(bf[2 * np][0], bf[2 * np][1], bf[2 * np + 1][0],
                      bf[2 * np + 1][1], sa + boff[np] + ks * 32);
#pragma unroll
            for (int mt = 0; mt < 4; mt++)
#pragma unroll
                for (int nt = 0; nt < 4; nt++)
                    mma16(acc[mt][nt], af[mt], bf[nt]);
        }
    }

    // ---- epilogue ----
    float inv[4][2];
    if (EPI == 4) {
#pragma unroll
        for (int nt = 0; nt < 4; nt++) {
            const int n0 = bn + wn * 32 + nt * 8 + cc * 2;
            inv[nt][0] = 1.0f / __ldg(&aux[blockIdx.z * SS + n0]);
            inv[nt][1] = 1.0f / __ldg(&aux[blockIdx.z * SS + n0 + 1]);
        }
    }
    float* srs = (float*)sm;   // EPI==3: per-CTA row sums (128 floats)
    if (EPI == 3) {
        __syncthreads();       // all warps done reading pipeline smem
        if (tid < 128) srs[tid] = 0.f;
        __syncthreads();
    }

#pragma unroll
    for (int mt = 0; mt < 4; mt++) {
        const int m0 = bm + wm * 64 + mt * 16 + qd;
        float rs0 = 0.f, rs1 = 0.f;          // EPI==3 row sums
        float mx0 = -INFINITY, mx1 = -INFINITY;   // EPI==4 row maxes
#pragma unroll
        for (int nt = 0; nt < 4; nt++) {
            const int n0 = bn + wn * 32 + nt * 8 + cc * 2;
            float c0 = acc[mt][nt][0] * scale;
            float c1 = acc[mt][nt][1] * scale;
            float c2 = acc[mt][nt][2] * scale;
            float c3 = acc[mt][nt][3] * scale;
            if (EPI == 4) {
                c0 *= inv[nt][0]; c1 *= inv[nt][1];
                c2 *= inv[nt][0]; c3 *= inv[nt][1];
                mx0 = fmaxf(mx0, fmaxf(c0, c1));
                mx1 = fmaxf(mx1, fmaxf(c2, c3));
            } else if (EPI == 3) {
                c0 = __expf(c0); c1 = __expf(c1);
                c2 = __expf(c2); c3 = __expf(c3);
                rs0 += c0 + c1; rs1 += c2 + c3;
                __half2 h0 = __floats2half2_rn(c0, c1);
                __half2 h1 = __floats2half2_rn(c2, c3);
                __half* Ch = (__half*)Cv + (size_t)blockIdx.z * sC;
                *(__half2*)(Ch + (size_t)m0 * ldc + n0)       = h0;
                *(__half2*)(Ch + (size_t)(m0 + 8) * ldc + n0) = h1;
            } else {
                const float bx = bias[n0], by = bias[n0 + 1];
                c0 += bx; c1 += by; c2 += bx; c3 += by;
                __half2 h0 = __floats2half2_rn(c0, c1);
                __half2 h1 = __floats2half2_rn(c2, c3);
                __half* Ch = (__half*)Cv + (size_t)blockIdx.z * sC;
                *(__half2*)(Ch + (size_t)m0 * ldc + n0)       = h0;
                *(__half2*)(Ch + (size_t)(m0 + 8) * ldc + n0) = h1;
                if (EPI == 2) {
                    const int b0 = m0 >> 11, s0 = m0 & (SS - 1);
                    __half* t = CT + ((size_t)b0 * QDIM + n0) * SS + s0;
                    t[0]      = __low2half(h0);
                    t[SS]     = __high2half(h0);
                    t[8]      = __low2half(h1);
                    t[SS + 8] = __high2half(h1);
                }
            }
        }
        if (EPI == 3) {
            rs0 += __shfl_xor_sync(0xffffffffu, rs0, 1);
            rs0 += __shfl_xor_sync(0xffffffffu, rs0, 2);
            rs1 += __shfl_xor_sync(0xffffffffu, rs1, 1);
            rs1 += __shfl_xor_sync(0xffffffffu, rs1, 2);
            if (cc == 0) {
                atomicAdd(&srs[wm * 64 + mt * 16 + qd],     rs0);
                atomicAdd(&srs[wm * 64 + mt * 16 + qd + 8], rs1);
            }
        }
        if (EPI == 4) {
            mx0 = fmaxf(mx0, __shfl_xor_sync(0xffffffffu, mx0, 1));
            mx0 = fmaxf(mx0, __shfl_xor_sync(0xffffffffu, mx0, 2));
            mx1 = fmaxf(mx1, __shfl_xor_sync(0xffffffffu, mx1, 1));
            mx1 = fmaxf(mx1, __shfl_xor_sync(0xffffffffu, mx1, 2));
            if (cc == 0) {
                atomicMaxF(&xmax[blockIdx.z * QDIM + m0],     mx0);
                atomicMaxF(&xmax[blockIdx.z * QDIM + m0 + 8], mx1);
            }
        }
    }
    if (EPI == 3) {
        __syncthreads();
        if (tid < 128) atomicAdd(&aux[blockIdx.z * SS + bm + tid], srs[tid]);
    }
}

// ============================================================================
// init: zero RS (65536 floats) and set XMAX (8192 floats) to -inf
// grid 72 x 256: blocks 0..63 -> RS, 64..71 -> XMAX
// ============================================================================
__global__ __launch_bounds__(256) void init_aux(float* __restrict__ rs,
                                                float* __restrict__ xmax)
{
    if (blockIdx.x < 64) {
        const int i = blockIdx.x * 1024 + threadIdx.x * 4;
        *(float4*)(rs + i) = make_float4(0.f, 0.f, 0.f, 0.f);
    } else {
        const int i = (blockIdx.x - 64) * 1024 + threadIdx.x * 4;
        const float ninf = -INFINITY;
        *(float4*)(xmax + i) = make_float4(ninf, ninf, ninf, ninf);
    }
}

// ============================================================================
// fp32 -> fp16 conversion (n % 8 == 0)
// ============================================================================
__global__ __launch_bounds__(256) void f2h_kernel(
    const float* __restrict__ s, __half* __restrict__ d, size_t n)
{
    const size_t i = ((size_t)blockIdx.x * 256 + threadIdx.x) * 8;
    if (i + 8 <= n) {
        float4 a = *(const float4*)(s + i);
        float4 b = *(const float4*)(s + i + 4);
        uint4 o;
        __half2 h;
        h = __floats2half2_rn(a.x, a.y); o.x = *(uint32_t*)&h;
        h = __floats2half2_rn(a.z, a.w); o.y = *(uint32_t*)&h;
        h = __floats2half2_rn(b.x, b.y); o.z = *(uint32_t*)&h;
        h = __floats2half2_rn(b.z, b.w); o.w = *(uint32_t*)&h;
        *(uint4*)(d + i) = o;
    }
}

// ============================================================================
__global__ __launch_bounds__(256) void final_head(
    const float* __restrict__ W3, const float* __restrict__ b3,
    float* __restrict__ out)
{
    const int b = blockIdx.x;
    const int tid = threadIdx.x;
    __shared__ float xs[QDIM];
    xs[tid] = g_XMAX[b * QDIM + tid];
    __syncthreads();

#pragma unroll
    for (int kk = 0; kk < 4; kk++) {
        const int o = tid + kk * 256;
        const float4* w = (const float4*)(W3 + (size_t)o * QDIM);
        float acc = 0.f;
#pragma unroll
        for (int qq = 0; qq < QDIM / 4; qq++) {
            float4 wv = w[qq];
            acc += wv.x * xs[qq * 4 + 0] + wv.y * xs[qq * 4 + 1]
                 + wv.z * xs[qq * 4 + 2] + wv.w * xs[qq * 4 + 3];
        }
        out[(size_t)b * ODIM + o] = fmaxf(acc + b3[o], 0.f);
    }
}

// ============================================================================
extern "C" void kernel_launch(void* const* d_in, const int* in_sizes, int n_in,
                              void* d_out, int out_size)
{
    const float* data = (const float*)d_in[0];
    /* d_in[1] = seq_len: unused by the reference */
    const float* W1 = (const float*)d_in[2];
    const float* b1 = (const float*)d_in[3];
    const float* W2 = (const float*)d_in[4];
    const float* b2 = (const float*)d_in[5];
    const float* W3 = (const float*)d_in[6];
    const float* b3 = (const float*)d_in[7];
    float* out = (float*)d_out;

    __half *dataH, *W1h, *W2h, *Qh, *Kh, *KTh, *EH;
    float *RS, *XMAX;
    cudaGetSymbolAddress((void**)&dataH, g_dataH);
    cudaGetSymbolAddress((void**)&W1h, g_W1h);
    cudaGetSymbolAddress((void**)&W2h, g_W2h);
    cudaGetSymbolAddress((void**)&Qh,  g_Qh);
    cudaGetSymbolAddress((void**)&Kh,  g_Kh);
    cudaGetSymbolAddress((void**)&KTh, g_KTh);
    cudaGetSymbolAddress((void**)&EH,  g_EH);
    cudaGetSymbolAddress((void**)&RS,  g_RS);
    cudaGetSymbolAddress((void**)&XMAX, g_XMAX);

    const int SMEM = STAGES * 10240 * 2;   // 81920 B
    cudaFuncSetAttribute(hgemm<1>, cudaFuncAttributeMaxDynamicSharedMemorySize, SMEM);
    cudaFuncSetAttribute(hgemm<2>, cudaFuncAttributeMaxDynamicSharedMemorySize, SMEM);
    cudaFuncSetAttribute(hgemm<3>, cudaFuncAttributeMaxDynamicSharedMemorySize, SMEM);
    cudaFuncSetAttribute(hgemm<4>, cudaFuncAttributeMaxDynamicSharedMemorySize, SMEM);

    const size_t strQK = (size_t)SS * QDIM;
    const size_t strSC = (size_t)SS * SS;
    const float  inv_sqrt_qd = 1.0f / 16.0f;

    // 0) convert inputs to fp16; init RS=0, XMAX=-inf
    const size_t nd = (size_t)BB * SS * DD;
    f2h_kernel<<<(unsigned)(nd / (256 * 8)), 256>>>(data, dataH, nd);
    f2h_kernel<<<(QDIM * DD) / (256 * 8), 256>>>(W1, W1h, QDIM * DD);
    f2h_kernel<<<(QDIM * DD) / (256 * 8), 256>>>(W2, W2h, QDIM * DD);
    init_aux<<<72, 256>>>(RS, XMAX);

    // 1) Q = data @ W1^T + b1 -> fp16
    hgemm<1><<<dim3(QDIM / 128, (BB * SS) / 128, 1), 256, SMEM>>>(
        dataH, W1h, b1, Qh, nullptr, nullptr, nullptr,
        DD, DD, QDIM, DD, 1.0f, 0, 0, 0);
    // 2) K = data @ W2^T + b2 -> fp16 + fp16 transposed
    hgemm<2><<<dim3(QDIM / 128, (BB * SS) / 128, 1), 256, SMEM>>>(
        dataH, W2h, b2, Kh, KTh, nullptr, nullptr,
        DD, DD, QDIM, DD, 1.0f, 0, 0, 0);

    // 3) E[b] = exp((K[b] @ Q[b]^T) / 16) -> fp16, rowsums into RS
    hgemm<3><<<dim3(SS / 128, SS / 128, BB), 256, SMEM>>>(
        Kh, Qh, nullptr, EH, nullptr, RS, nullptr,
        QDIM, QDIM, SS, QDIM, inv_sqrt_qd, strQK, strQK, strSC);

    // 4) X[q,s] = (KT[b] @ E[b]^T) / RS[b][s]; fused max over s -> XMAX
    hgemm<4><<<dim3(SS / 128, QDIM / 128, BB), 256, SMEM>>>(
        KTh, EH, nullptr, nullptr, nullptr, RS, XMAX,
        SS, SS, SS, SS, 1.0f, strQK, strSC, 0);

    // 5) out = relu(xmax @ W3^T + b3)
    final_head<<<BB, 256>>>(W3, b3, out);
}

// round 10
// speedup vs baseline: 1.1939x; 1.0083x over previous
#include <cuda_runtime.h>
#include <cuda_fp16.h>
#include <cstdint>

#define BB  32
#define SS  2048
#define DD  768
#define QDIM 256
#define ODIM 1024
#define STAGES 4

// -------- scratch (allocation-free: __device__ globals) --------
__device__ __half g_dataH[(size_t)BB * SS * DD];
__device__ __half g_W12h[2 * QDIM * DD];           // [W1; W2] rows 0-255 / 256-511
__device__ float  g_B12[2 * QDIM];                 // [b1; b2]
__device__ __half g_QKh[(size_t)BB * SS * 2 * QDIM]; // per row: Q[0:256] K[256:512]
__device__ __half g_KTh[(size_t)BB * QDIM * SS];   // K transposed [b][q][s]
__device__ __half g_EH [(size_t)BB * SS * SS];     // exp(scores) fp16 (256 MB)
__device__ float  g_RS [BB * SS];                  // row sums of exp
__device__ float  g_XMAX[BB * QDIM];               // fused maxpool result

__device__ __forceinline__ uint32_t smem_u32(const void* p) {
    uint32_t a;
    asm("{ .reg .u64 t; cvta.to.shared.u64 t, %1; cvt.u32.u64 %0, t; }" : "=r"(a) : "l"(p));
    return a;
}
__device__ __forceinline__ void cp16(uint32_t dst, const void* src) {
    asm volatile("cp.async.cg.shared.global [%0], [%1], 16;" :: "r"(dst), "l"(src));
}
#define CP_COMMIT() asm volatile("cp.async.commit_group;" ::: "memory")
#define CP_WAIT(n)  asm volatile("cp.async.wait_group %0;" :: "n"(n) : "memory")

__device__ __forceinline__ void ldsm4(uint32_t& r0, uint32_t& r1, uint32_t& r2,
                                      uint32_t& r3, uint32_t addr) {
    asm volatile("ldmatrix.sync.aligned.m8n8.x4.shared.b16 {%0,%1,%2,%3}, [%4];"
                 : "=r"(r0), "=r"(r1), "=r"(r2), "=r"(r3) : "r"(addr));
}

__device__ __forceinline__ void mma16(float* d, const uint32_t* a, const uint32_t* b) {
    asm volatile(
        "mma.sync.aligned.m16n8k16.row.col.f32.f16.f16.f32 "
        "{%0,%1,%2,%3}, {%4,%5,%6,%7}, {%8,%9}, {%0,%1,%2,%3};"
        : "+f"(d[0]), "+f"(d[1]), "+f"(d[2]), "+f"(d[3])
        : "r"(a[0]), "r"(a[1]), "r"(a[2]), "r"(a[3]), "r"(b[0]), "r"(b[1]));
}

// exact, order-independent float atomic max (init must be -inf)
__device__ __forceinline__ void atomicMaxF(float* a, float v) {
    if (v >= 0.f) atomicMax((int*)a, __float_as_int(v));
    else          atomicMin((unsigned int*)a, __float_as_uint(v));
}

// ============================================================================
// fp16 NT GEMM, cp.async 4-stage pipeline + ldmatrix fragment loads.
// CTA 128x128, k-chunk 32, 256 thr (8 warps 2x4), warp tile 64x32.
// A [M,K], B [N,K] fp16 row-major.
//   EPI=2: C fp16 + bias; if bn>=256 ALSO CT fp16 transposed per-batch
//          [QDIM][SS] at q = n-256 (merged QK projection)
//   EPI=3: C fp16 = exp(acc*scale); per-row sums atomically added to aux[b*SS+m]
//   EPI=4: no C store; X[m,n] = acc / aux[b*SS+n]; row-max over n fused:
//          atomicMaxF into xmax[b*QDIM+m]
// Smem rows padded to 40 halves (80B): conflict-free ldmatrix.
// Requires M%128==0, N%128==0, kdim%32==0.
// ============================================================================
template <int EPI>
__global__ __launch_bounds__(256, 2) void hgemm(
    const __half* __restrict__ A, const __half* __restrict__ B,
    const float* __restrict__ bias, void* __restrict__ Cv,
    __half* __restrict__ CT, float* __restrict__ aux, float* __restrict__ xmax,
    int lda, int ldb, int ldc, int kdim, float scale,
    size_t sA, size_t sB, size_t sC)
{
    extern __shared__ __half sm[];
    A += (size_t)blockIdx.z * sA;
    B += (size_t)blockIdx.z * sB;
    const int bm = blockIdx.y * 128;
    const int bn = blockIdx.x * 128;

    const int tid = threadIdx.x;
    const int lane = tid & 31, wid = tid >> 5;
    const int wm = wid & 1, wn = wid >> 1;      // warp 64m x 32n
    const int qd = lane >> 2, cc = lane & 3;

    // loader: thread covers row = tid>>1, halves [seg, seg+16)
    const int lrow = tid >> 1;
    const int lseg = (tid & 1) * 16;
    const __half* pa = A + (size_t)(bm + lrow) * lda + lseg;
    const __half* pb = B + (size_t)(bn + lrow) * ldb + lseg;
    const uint32_t smb = smem_u32(sm);
    const uint32_t dA = smb + (uint32_t)(lrow * 40 + lseg) * 2;
    const uint32_t dB = dA + 5120 * 2;
    const uint32_t STG = 10240 * 2;             // bytes per stage (A+B)

    // ldmatrix per-lane offsets (relative to stage base, ks=0)
    uint32_t aoff[4], boff[2];
#pragma unroll
    for (int mt = 0; mt < 4; mt++)
        aoff[mt] = (uint32_t)(((wm * 64 + mt * 16 + (lane & 7) + (lane & 8)) * 40
                               + ((lane >> 4) * 8)) * 2);
#pragma unroll
    for (int np = 0; np < 2; np++)
        boff[np] = (uint32_t)(5120 * 2
                   + ((wn * 32 + np * 16 + (lane & 7) + ((lane >> 4) * 8)) * 40
                      + (lane & 8)) * 2);

    float acc[4][4][4];
#pragma unroll
    for (int i = 0; i < 4; i++)
#pragma unroll
        for (int j = 0; j < 4; j++)
#pragma unroll
            for (int r = 0; r < 4; r++) acc[i][j][r] = 0.f;

    const int nc = kdim >> 5;

    // prologue: stages 0..STAGES-2
#pragma unroll
    for (int s = 0; s < STAGES - 1; s++) {
        if (s < nc) {
            const size_t k0 = (size_t)s * 32;
            const uint32_t da = dA + s * STG, db = dB + s * STG;
            cp16(da,      pa + k0);
            cp16(da + 16, pa + k0 + 8);
            cp16(db,      pb + k0);
            cp16(db + 16, pb + k0 + 8);
        }
        CP_COMMIT();
    }

    for (int ch = 0; ch < nc; ch++) {
        CP_WAIT(STAGES - 2);
        __syncthreads();   // stage ch ready; everyone done reading stage ch-1

        // refill the stage freed by chunk ch-1
        {
            const int nxt = ch + STAGES - 1;
            if (nxt < nc) {
                const int st = nxt & (STAGES - 1);
                const size_t k0 = (size_t)nxt * 32;
                const uint32_t da = dA + st * STG, db = dB + st * STG;
                cp16(da,      pa + k0);
                cp16(da + 16, pa + k0 + 8);
                cp16(db,      pb + k0);
                cp16(db + 16, pb + k0 + 8);
            }
            CP_COMMIT();
        }

        const uint32_t sa = smb + (uint32_t)(ch & (STAGES - 1)) * STG;
#pragma unroll
        for (int ks = 0; ks < 2; ks++) {
            uint32_t af[4][4], bf[4][2];
#pragma unroll
            for (int mt = 0; mt < 4; mt++)
                ldsm4(af[mt][0], af[mt][1], af[mt][2], af[mt][3],
                      sa + aoff[mt] + ks * 32);
#pragma unroll
            for (int np = 0; np < 2; np++)
                ldsm4(bf[2 * np][0], bf[2 * np][1], bf[2 * np + 1][0],
                      bf[2 * np + 1][1], sa + boff[np] + ks * 32);
#pragma unroll
            for (int mt = 0; mt < 4; mt++)
#pragma unroll
                for (int nt = 0; nt < 4; nt++)
                    mma16(acc[mt][nt], af[mt], bf[nt]);
        }
    }

    // ---- epilogue ----
    float inv[4][2];
    if (EPI == 4) {
#pragma unroll
        for (int nt = 0; nt < 4; nt++) {
            const int n0 = bn + wn * 32 + nt * 8 + cc * 2;
            inv[nt][0] = 1.0f / __ldg(&aux[blockIdx.z * SS + n0]);
            inv[nt][1] = 1.0f / __ldg(&aux[blockIdx.z * SS + n0 + 1]);
        }
    }
    float* srs = (float*)sm;   // EPI==3: per-CTA row sums (128 floats)
    if (EPI == 3) {
        __syncthreads();       // all warps done reading pipeline smem
        if (tid < 128) srs[tid] = 0.f;
        __syncthreads();
    }

#pragma unroll
    for (int mt = 0; mt < 4; mt++) {
        const int m0 = bm + wm * 64 + mt * 16 + qd;
        float rs0 = 0.f, rs1 = 0.f;               // EPI==3 row sums
        float mx0 = -INFINITY, mx1 = -INFINITY;   // EPI==4 row maxes
#pragma unroll
        for (int nt = 0; nt < 4; nt++) {
            const int n0 = bn + wn * 32 + nt * 8 + cc * 2;
            float c0 = acc[mt][nt][0] * scale;
            float c1 = acc[mt][nt][1] * scale;
            float c2 = acc[mt][nt][2] * scale;
            float c3 = acc[mt][nt][3] * scale;
            if (EPI == 4) {
                c0 *= inv[nt][0]; c1 *= inv[nt][1];
                c2 *= inv[nt][0]; c3 *= inv[nt][1];
                mx0 = fmaxf(mx0, fmaxf(c0, c1));
                mx1 = fmaxf(mx1, fmaxf(c2, c3));
            } else if (EPI == 3) {
                c0 = __expf(c0); c1 = __expf(c1);
                c2 = __expf(c2); c3 = __expf(c3);
                rs0 += c0 + c1; rs1 += c2 + c3;
                __half2 h0 = __floats2half2_rn(c0, c1);
                __half2 h1 = __floats2half2_rn(c2, c3);
                __half* Ch = (__half*)Cv + (size_t)blockIdx.z * sC;
                *(__half2*)(Ch + (size_t)m0 * ldc + n0)       = h0;
                *(__half2*)(Ch + (size_t)(m0 + 8) * ldc + n0) = h1;
            } else {  // EPI == 2: merged QK projection
                const float bx = bias[n0], by = bias[n0 + 1];
                c0 += bx; c1 += by; c2 += bx; c3 += by;
                __half2 h0 = __floats2half2_rn(c0, c1);
                __half2 h1 = __floats2half2_rn(c2, c3);
                __half* Ch = (__half*)Cv + (size_t)blockIdx.z * sC;
                *(__half2*)(Ch + (size_t)m0 * ldc + n0)       = h0;
                *(__half2*)(Ch + (size_t)(m0 + 8) * ldc + n0) = h1;
                if (bn >= 256) {   // K columns -> transposed copy
                    const int b0 = m0 >> 11, s0 = m0 & (SS - 1);
                    __half* t = CT + ((size_t)b0 * QDIM + (n0 - 256)) * SS + s0;
                    t[0]      = __low2half(h0);
                    t[SS]     = __high2half(h0);
                    t[8]      = __low2half(h1);
                    t[SS + 8] = __high2half(h1);
                }
            }
        }
        if (EPI == 3) {
            rs0 += __shfl_xor_sync(0xffffffffu, rs0, 1);
            rs0 += __shfl_xor_sync(0xffffffffu, rs0, 2);
            rs1 += __shfl_xor_sync(0xffffffffu, rs1, 1);
            rs1 += __shfl_xor_sync(0xffffffffu, rs1, 2);
            if (cc == 0) {
                atomicAdd(&srs[wm * 64 + mt * 16 + qd],     rs0);
                atomicAdd(&srs[wm * 64 + mt * 16 + qd + 8], rs1);
            }
        }
        if (EPI == 4) {
            mx0 = fmaxf(mx0, __shfl_xor_sync(0xffffffffu, mx0, 1));
            mx0 = fmaxf(mx0, __shfl_xor_sync(0xffffffffu, mx0, 2));
            mx1 = fmaxf(mx1, __shfl_xor_sync(0xffffffffu, mx1, 1));
            mx1 = fmaxf(mx1, __shfl_xor_sync(0xffffffffu, mx1, 2));
            if (cc == 0) {
                atomicMaxF(&xmax[blockIdx.z * QDIM + m0],     mx0);
                atomicMaxF(&xmax[blockIdx.z * QDIM + m0 + 8], mx1);
            }
        }
    }
    if (EPI == 3) {
        __syncthreads();
        if (tid < 128) atomicAdd(&aux[blockIdx.z * SS + bm + tid], srs[tid]);
    }
}

// ============================================================================
// init: RS=0 (64 blocks), XMAX=-inf (8 blocks), B12 = [b1;b2] (2 blocks)
// ============================================================================
__global__ __launch_bounds__(256) void init_aux(
    float* __restrict__ rs, float* __restrict__ xmax,
    const float* __restrict__ b1, const float* __restrict__ b2,
    float* __restrict__ b12)
{
    if (blockIdx.x < 64) {
        const int i = blockIdx.x * 1024 + threadIdx.x * 4;
        *(float4*)(rs + i) = make_float4(0.f, 0.f, 0.f, 0.f);
    } else if (blockIdx.x < 72) {
        const int i = (blockIdx.x - 64) * 1024 + threadIdx.x * 4;
        const float ninf = -INFINITY;
        *(float4*)(xmax + i) = make_float4(ninf, ninf, ninf, ninf);
    } else if (blockIdx.x == 72) {
        b12[threadIdx.x] = b1[threadIdx.x];
    } else {
        b12[256 + threadIdx.x] = b2[threadIdx.x];
    }
}

// ============================================================================
// fp32 -> fp16 conversion (n % 8 == 0)
// ============================================================================
__global__ __launch_bounds__(256) void f2h_kernel(
    const float* __restrict__ s, __half* __restrict__ d, size_t n)
{
    const size_t i = ((size_t)blockIdx.x * 256 + threadIdx.x) * 8;
    if (i + 8 <= n) {
        float4 a = *(const float4*)(s + i);
        float4 b = *(const float4*)(s + i + 4);
        uint4 o;
        __half2 h;
        h = __floats2half2_rn(a.x, a.y); o.x = *(uint32_t*)&h;
        h = __floats2half2_rn(a.z, a.w); o.y = *(uint32_t*)&h;
        h = __floats2half2_rn(b.x, b.y); o.z = *(uint32_t*)&h;
        h = __floats2half2_rn(b.z, b.w); o.w = *(uint32_t*)&h;
        *(uint4*)(d + i) = o;
    }
}

// ============================================================================
__global__ __launch_bounds__(256) void final_head(
    const float* __restrict__ W3, const float* __restrict__ b3,
    float* __restrict__ out)
{
    const int b = blockIdx.x;
    const int tid = threadIdx.x;
    __shared__ float xs[QDIM];
    xs[tid] = g_XMAX[b * QDIM + tid];
    __syncthreads();

#pragma unroll
    for (int kk = 0; kk < 4; kk++) {
        const int o = tid + kk * 256;
        const float4* w = (const float4*)(W3 + (size_t)o * QDIM);
        float acc = 0.f;
#pragma unroll
        for (int qq = 0; qq < QDIM / 4; qq++) {
            float4 wv = w[qq];
            acc += wv.x * xs[qq * 4 + 0] + wv.y * xs[qq * 4 + 1]
                 + wv.z * xs[qq * 4 + 2] + wv.w * xs[qq * 4 + 3];
        }
        out[(size_t)b * ODIM + o] = fmaxf(acc + b3[o], 0.f);
    }
}

// ============================================================================
extern "C" void kernel_launch(void* const* d_in, const int* in_sizes, int n_in,
                              void* d_out, int out_size)
{
    const float* data = (const float*)d_in[0];
    /* d_in[1] = seq_len: unused by the reference */
    const float* W1 = (const float*)d_in[2];
    const float* b1 = (const float*)d_in[3];
    const float* W2 = (const float*)d_in[4];
    const float* b2 = (const float*)d_in[5];
    const float* W3 = (const float*)d_in[6];
    const float* b3 = (const float*)d_in[7];
    float* out = (float*)d_out;

    __half *dataH, *W12h, *QKh, *KTh, *EH;
    float *B12, *RS, *XMAX;
    cudaGetSymbolAddress((void**)&dataH, g_dataH);
    cudaGetSymbolAddress((void**)&W12h, g_W12h);
    cudaGetSymbolAddress((void**)&B12,  g_B12);
    cudaGetSymbolAddress((void**)&QKh,  g_QKh);
    cudaGetSymbolAddress((void**)&KTh,  g_KTh);
    cudaGetSymbolAddress((void**)&EH,   g_EH);
    cudaGetSymbolAddress((void**)&RS,   g_RS);
    cudaGetSymbolAddress((void**)&XMAX, g_XMAX);

    const int SMEM = STAGES * 10240 * 2;   // 81920 B
    cudaFuncSetAttribute(hgemm<2>, cudaFuncAttributeMaxDynamicSharedMemorySize, SMEM);
    cudaFuncSetAttribute(hgemm<3>, cudaFuncAttributeMaxDynamicSharedMemorySize, SMEM);
    cudaFuncSetAttribute(hgemm<4>, cudaFuncAttributeMaxDynamicSharedMemorySize, SMEM);

    const size_t strQK = (size_t)SS * 2 * QDIM;   // per-batch stride in QKh
    const size_t strKT = (size_t)QDIM * SS;
    const size_t strSC = (size_t)SS * SS;
    const float  inv_sqrt_qd = 1.0f / 16.0f;

    // 0) convert inputs to fp16; init RS=0, XMAX=-inf, B12=[b1;b2]
    const size_t nd = (size_t)BB * SS * DD;
    f2h_kernel<<<(unsigned)(nd / (256 * 8)), 256>>>(data, dataH, nd);
    f2h_kernel<<<(QDIM * DD) / (256 * 8), 256>>>(W1, W12h, QDIM * DD);
    f2h_kernel<<<(QDIM * DD) / (256 * 8), 256>>>(W2, W12h + QDIM * DD, QDIM * DD);
    init_aux<<<74, 256>>>(RS, XMAX, b1, b2, B12);

    // 1) QK = data @ [W1;W2]^T + [b1;b2] -> fp16 [BS][512]; K part also -> KTh
    hgemm<2><<<dim3(512 / 128, (BB * SS) / 128, 1), 256, SMEM>>>(
        dataH, W12h, B12, QKh, KTh, nullptr, nullptr,
        DD, DD, 2 * QDIM, DD, 1.0f, 0, 0, 0);

    // 2) E[b] = exp((K[b] @ Q[b]^T) / 16) -> fp16, rowsums into RS
    //    A = K rows (QKh+256, lda=512), B = Q rows (QKh, ldb=512)
    hgemm<3><<<dim3(SS / 128, SS / 128, BB), 256, SMEM>>>(
        QKh + 256, QKh, nullptr, EH, nullptr, RS, nullptr,
        2 * QDIM, 2 * QDIM, SS, QDIM, inv_sqrt_qd, strQK, strQK, strSC);

    // 3) X[q,s] = (KT[b] @ E[b]^T) / RS[b][s]; fused max over s -> XMAX
    hgemm<4><<<dim3(SS / 128, QDIM / 128, BB), 256, SMEM>>>(
        KTh, EH, nullptr, nullptr, nullptr, RS, XMAX,
        SS, SS, SS, SS, 1.0f, strKT, strSC, 0);

    // 4) out = relu(xmax @ W3^T + b3)
    final_head<<<BB, 256>>>(W3, b3, out);
}